// round 14
// baseline (speedup 1.0000x reference)
#include <cuda_runtime.h>
#include <cuda_fp16.h>
#include <math.h>
#include <stdint.h>

#define BATCH 2
#define CH    512
#define CQ    64
#define NPIX  4096

#define BS_XT (NPIX * CH)
#define BS_P  (NPIX * 128)
#define BS_F  (CH * NPIX)
#define BS_S  ((long)NPIX * NPIX)

typedef __half fp16;

// ---------------- static scratch ----------------
__device__ __align__(128) fp16  g_xTh[4L * NPIX * CH];
__device__ __align__(128) fp16  g_xTl[4L * NPIX * CH];
__device__ __align__(128) fp16  g_xcTh[2L * NPIX * CH];
__device__ __align__(128) fp16  g_xcTl[2L * NPIX * CH];
__device__ __align__(128) fp16  g_Wbch[128 * CH];
__device__ __align__(128) fp16  g_Wbcl[128 * CH];
__device__ __align__(128) fp16  g_Wdh[CH * CH];
__device__ __align__(128) fp16  g_Wdl[CH * CH];
__device__ __align__(128) fp16  g_Ph[4L * NPIX * 128];
__device__ __align__(128) fp16  g_Pl[4L * NPIX * 128];
__device__ __align__(128) fp16  g_Fh[(long)BATCH * CH * NPIX];
__device__ __align__(128) float g_S12[(size_t)BATCH * NPIX * NPIX];
__device__ __align__(128) float g_S21[(size_t)BATCH * NPIX * NPIX];
__device__ __align__(128) fp16  g_Ah[(size_t)BATCH * NPIX * NPIX];
__device__ float g_scal[4];
__device__ float g_bias2[128];

__device__ __forceinline__ void split2(float v, fp16& h, fp16& l) {
    h = __float2half_rn(v);
    l = __float2half_rn(v - __half2float(h));
}

__device__ __forceinline__ float fexp(float x) {
    float t = x * 1.4426950408889634f;
    t = fmaxf(t, -125.0f);
    float r = rintf(t);
    float f = t - r;
    float p = 1.3333558e-3f;
    p = fmaf(p, f, 9.6181291e-3f);
    p = fmaf(p, f, 5.5504109e-2f);
    p = fmaf(p, f, 2.4022651e-1f);
    p = fmaf(p, f, 6.9314718e-1f);
    p = fmaf(p, f, 1.0f);
    float sc = __int_as_float(((int)r + 127) << 23);
    return p * sc;
}

// ---------------- prep ----------------
__global__ void prep_kernel(const float* bb, const float* bc,
                            const float* a, const float* b) {
    int t = threadIdx.x;
    if (t < 64)       g_bias2[t] = bb[t];
    else if (t < 128) g_bias2[t] = bc[t - 64];
    if (t == 0) { g_scal[0] = a[0]; g_scal[1] = b[0]; g_scal[2] = a[0] + b[0]; }
}

__global__ void split_kernel(const float* __restrict__ src,
                             fp16* __restrict__ hi, fp16* __restrict__ lo, int n) {
    int i = blockIdx.x * blockDim.x + threadIdx.x;
    if (i < n) { fp16 h, l; split2(src[i], h, l); hi[i] = h; lo[i] = l; }
}

__global__ void wbc_split_kernel(const float* __restrict__ Wb,
                                 const float* __restrict__ Wc) {
    int i = blockIdx.x * blockDim.x + threadIdx.x;
    if (i < 128 * CH) {
        float v = (i < 64 * CH) ? Wb[i] : Wc[i - 64 * CH];
        fp16 h, l; split2(v, h, l);
        g_Wbch[i] = h; g_Wbcl[i] = l;
    }
}

// ---------------- combine + transpose + split ----------------
__global__ void __launch_bounds__(256) transcomb_kernel(
    const float* __restrict__ x1, const float* __restrict__ x2) {
    __shared__ float t1[32][33], t2[32][33];
    const int b  = blockIdx.z;
    const int n0 = blockIdx.x * 32;
    const int k0 = blockIdx.y * 32;
    const int tx = threadIdx.x, ty = threadIdx.y;
    const float al = g_scal[0], be = g_scal[1];

    const long inb = (long)b * CH * NPIX;
#pragma unroll
    for (int it = 0; it < 4; it++) {
        int ki = ty + it * 8;
        t1[ki][tx] = x1[inb + (long)(k0 + ki) * NPIX + n0 + tx];
        t2[ki][tx] = x2[inb + (long)(k0 + ki) * NPIX + n0 + tx];
    }
    __syncthreads();

#pragma unroll
    for (int it = 0; it < 4; it++) {
        int ni = ty + it * 8;
        float v1 = t1[tx][ni];
        float v2 = t2[tx][ni];
        float vc = al * v1 + be * v2;
        long o1 = ((long)b * NPIX + n0 + ni) * CH + k0 + tx;
        long o2 = ((long)(2 + b) * NPIX + n0 + ni) * CH + k0 + tx;
        long oc = ((long)b * NPIX + n0 + ni) * CH + k0 + tx;
        fp16 h, l;
        split2(v1, h, l); g_xTh[o1] = h; g_xTl[o1] = l;
        split2(v2, h, l); g_xTh[o2] = h; g_xTl[o2] = l;
        split2(vc, h, l); g_xcTh[oc] = h; g_xcTl[oc] = l;
    }
}

// ---------------- fused double-softmax abs-diff (per-batch) ----------------
__global__ void __launch_bounds__(256) softdiff_kernel(int batch) {
    const long row = (long)batch * NPIX + blockIdx.x;
    const float4* p12 = (const float4*)(g_S12 + row * (long)NPIX);
    const float4* p21 = (const float4*)(g_S21 + row * (long)NPIX);
    __half2* oh = (__half2*)(g_Ah + row * (long)NPIX);
    const int t = threadIdx.x;
    constexpr int PER = NPIX / (256 * 4);

    float4 v12[PER], v21[PER];
    float mx12 = -1e30f, mx21 = -1e30f;
#pragma unroll
    for (int i = 0; i < PER; i++) {
        v12[i] = p12[t + i * 256];
        v21[i] = p21[t + i * 256];
        mx12 = fmaxf(mx12, fmaxf(fmaxf(v12[i].x, v12[i].y), fmaxf(v12[i].z, v12[i].w)));
        mx21 = fmaxf(mx21, fmaxf(fmaxf(v21[i].x, v21[i].y), fmaxf(v21[i].z, v21[i].w)));
    }
    __shared__ float red[2][8];
#pragma unroll
    for (int o = 16; o > 0; o >>= 1) {
        mx12 = fmaxf(mx12, __shfl_xor_sync(0xffffffffu, mx12, o));
        mx21 = fmaxf(mx21, __shfl_xor_sync(0xffffffffu, mx21, o));
    }
    if ((t & 31) == 0) { red[0][t >> 5] = mx12; red[1][t >> 5] = mx21; }
    __syncthreads();
    mx12 = red[0][0]; mx21 = red[1][0];
#pragma unroll
    for (int w = 1; w < 8; w++) {
        mx12 = fmaxf(mx12, red[0][w]);
        mx21 = fmaxf(mx21, red[1][w]);
    }
    __syncthreads();

    float s12 = 0.0f, s21 = 0.0f;
#pragma unroll
    for (int i = 0; i < PER; i++) {
        v12[i].x = fexp(v12[i].x - mx12); v12[i].y = fexp(v12[i].y - mx12);
        v12[i].z = fexp(v12[i].z - mx12); v12[i].w = fexp(v12[i].w - mx12);
        v21[i].x = fexp(v21[i].x - mx21); v21[i].y = fexp(v21[i].y - mx21);
        v21[i].z = fexp(v21[i].z - mx21); v21[i].w = fexp(v21[i].w - mx21);
        s12 += (v12[i].x + v12[i].y) + (v12[i].z + v12[i].w);
        s21 += (v21[i].x + v21[i].y) + (v21[i].z + v21[i].w);
    }
#pragma unroll
    for (int o = 16; o > 0; o >>= 1) {
        s12 += __shfl_xor_sync(0xffffffffu, s12, o);
        s21 += __shfl_xor_sync(0xffffffffu, s21, o);
    }
    if ((t & 31) == 0) { red[0][t >> 5] = s12; red[1][t >> 5] = s21; }
    __syncthreads();
    s12 = red[0][0]; s21 = red[1][0];
#pragma unroll
    for (int w = 1; w < 8; w++) { s12 += red[0][w]; s21 += red[1][w]; }

    const float i12 = 1.0f / s12;
    const float i21 = 1.0f / s21;
#pragma unroll
    for (int i = 0; i < PER; i++) {
        float a0 = fabsf(v12[i].x * i12 - v21[i].x * i21);
        float a1 = fabsf(v12[i].y * i12 - v21[i].y * i21);
        float a2 = fabsf(v12[i].z * i12 - v21[i].z * i21);
        float a3 = fabsf(v12[i].w * i12 - v21[i].w * i21);
        __half2 h0; h0.x = __float2half_rn(a0); h0.y = __float2half_rn(a1);
        __half2 h1; h1.x = __float2half_rn(a2); h1.y = __float2half_rn(a3);
        oh[(t + i * 256) * 2]     = h0;
        oh[(t + i * 256) * 2 + 1] = h1;
    }
}

// ================= shared HMMA machinery (4-stage, WIDE 4-warp) ============
#define STAGE_B (2 * 128 * 80)
#define NSTAGE  4
#define SMEM_DYN (NSTAGE * STAGE_B)   // 81920

__device__ __forceinline__ uint32_t smem_u32(const void* p) {
    uint32_t a;
    asm("{ .reg .u64 t; cvta.to.shared.u64 t, %1; cvt.u32.u64 %0, t; }" : "=r"(a) : "l"(p));
    return a;
}
__device__ __forceinline__ void cp16(uint32_t dst, const void* src) {
    asm volatile("cp.async.cg.shared.global [%0], [%1], 16;" :: "r"(dst), "l"(src));
}
__device__ __forceinline__ void ldsm4(uint32_t* r, uint32_t addr) {
    asm volatile("ldmatrix.sync.aligned.m8n8.x4.shared.b16 {%0,%1,%2,%3}, [%4];"
                 : "=r"(r[0]), "=r"(r[1]), "=r"(r[2]), "=r"(r[3]) : "r"(addr));
}
__device__ __forceinline__ void mma16816(float* d, const uint32_t* a, const uint32_t* b) {
    asm volatile(
        "mma.sync.aligned.m16n8k16.row.col.f32.f16.f16.f32 "
        "{%0,%1,%2,%3}, {%4,%5,%6,%7}, {%8,%9}, {%0,%1,%2,%3};"
        : "+f"(d[0]), "+f"(d[1]), "+f"(d[2]), "+f"(d[3])
        : "r"(a[0]), "r"(a[1]), "r"(a[2]), "r"(a[3]), "r"(b[0]), "r"(b[1]));
}
__device__ __forceinline__ void waitg(int pend) {
    if (pend >= 2)      asm volatile("cp.async.wait_group 2;");
    else if (pend == 1) asm volatile("cp.async.wait_group 1;");
    else                asm volatile("cp.async.wait_group 0;");
}

// WIDE mainloop: 128 threads, 4 warps of 64x64, acc[4][8][4]
#define GEMM_MAINLOOP_W(LOADER)                                                \
    LOADER(0, 0);                                                              \
    if (nkt > 1) LOADER(1, 1);                                                 \
    if (nkt > 2) LOADER(2, 2);                                                 \
    int cons = 0, ld = 3;                                                      \
    for (int g = 0; g < nkt; g++) {                                            \
        waitg(nkt - 1 - g);                                                    \
        __syncthreads();                                                       \
        if (g + 3 < nkt) { LOADER(g + 3, ld); ld++; if (ld == NSTAGE) ld = 0; }\
        const uint32_t da = s0 + cons * STAGE_B;                               \
        const uint32_t db = da + 128 * 80;                                     \
        _Pragma("unroll")                                                      \
        for (int ks = 0; ks < 2; ks++) {                                       \
            uint32_t af[4][4];                                                 \
            _Pragma("unroll")                                                  \
            for (int mt = 0; mt < 4; mt++) {                                   \
                int row = wm * 64 + mt * 16 + (lane & 15);                     \
                int kc  = ks * 16 + (lane >> 4) * 8;                           \
                ldsm4(af[mt], da + row * 80 + kc * 2);                         \
            }                                                                  \
            uint32_t bfr[4][4];                                                \
            _Pragma("unroll")                                                  \
            for (int p = 0; p < 4; p++) {                                      \
                int row = wn * 64 + p * 16 + (lane >> 4) * 8 + (lane & 7);     \
                int kc  = ks * 16 + ((lane >> 3) & 1) * 8;                     \
                ldsm4(bfr[p], db + row * 80 + kc * 2);                         \
            }                                                                  \
            _Pragma("unroll")                                                  \
            for (int mt = 0; mt < 4; mt++)                                     \
                _Pragma("unroll")                                              \
                for (int p = 0; p < 4; p++) {                                  \
                    mma16816(acc[mt][2 * p],     af[mt], &bfr[p][0]);          \
                    mma16816(acc[mt][2 * p + 1], af[mt], &bfr[p][2]);          \
                }                                                              \
        }                                                                      \
        cons++; if (cons == NSTAGE) cons = 0;                                  \
    }

// ===== logits GEMM (WIDE, per-batch, 2 TERMS: Ph·Bh + Pl·Bh) =====
// z in [0,2): which matrix (0: S12, 1: S21). batch passed as param.
__global__ void __launch_bounds__(128, 2) logits_kernel(
    const fp16* __restrict__ Ph, const fp16* __restrict__ Pl,
    float* __restrict__ S12, float* __restrict__ S21, int batch)
{
    extern __shared__ __align__(16) fp16 dsm[];

    const int tid = threadIdx.x;
    const int wid = tid >> 5;
    const int lane = tid & 31;
    const int wm = wid >> 1;
    const int wn = wid & 1;
    const int m0 = blockIdx.y * 128;
    const int n0 = blockIdx.x * 128;
    const int which = blockIdx.z;
    const uint32_t s0 = smem_u32(dsm);

    const int aPlane = which ? (2 + batch) : batch;
    const int bPlane = which ? batch : (2 + batch);
    const fp16* a0 = Ph + (long)aPlane * BS_P;
    const fp16* a1 = Pl + (long)aPlane * BS_P;
    const fp16* b0 = Ph + (long)bPlane * BS_P + 64;
    const fp16* b1 = b0;                         // Bh for both terms
    float* C = (which ? S21 : S12) + (long)batch * BS_S;

    const int nkt = 4, lda = 128, ldb = 128;     // 2 k-chunks x 2 terms

    float acc[4][8][4];
#pragma unroll
    for (int i = 0; i < 4; i++)
#pragma unroll
        for (int j = 0; j < 8; j++)
#pragma unroll
            for (int q = 0; q < 4; q++) acc[i][j][q] = 0.0f;

    const int lrow0 = tid >> 2;
    const int lch0  = tid & 3;
#define LOAD_G(g, slot) do {                                                   \
        const int t_ = (g) % 2;                                                \
        const int k0_ = ((g) / 2) * 32;                                        \
        const fp16* Ap = (t_ == 0 ? a0 : a1) + (long)m0 * lda + k0_;           \
        const fp16* Bp = (t_ == 0 ? b0 : b1) + (long)n0 * ldb + k0_;           \
        const uint32_t da_ = s0 + (slot) * STAGE_B;                            \
        const uint32_t db_ = da_ + 128 * 80;                                   \
        _Pragma("unroll")                                                      \
        for (int i_ = 0; i_ < 4; i_++) {                                       \
            int row_ = lrow0 + i_ * 32;                                        \
            cp16(da_ + row_ * 80 + lch0 * 16, Ap + (long)row_ * lda + lch0 * 8);\
            cp16(db_ + row_ * 80 + lch0 * 16, Bp + (long)row_ * ldb + lch0 * 8);\
        }                                                                      \
        asm volatile("cp.async.commit_group;");                                \
    } while (0)

    GEMM_MAINLOOP_W(LOAD_G)
#undef LOAD_G

#pragma unroll
    for (int mt = 0; mt < 4; mt++) {
        const int mA = m0 + wm * 64 + mt * 16 + (lane >> 2);
#pragma unroll
        for (int nt = 0; nt < 8; nt++) {
            const int n = n0 + wn * 64 + nt * 8 + (lane & 3) * 2;
            *(float2*)(C + (long)mA * NPIX + n)       = make_float2(acc[mt][nt][0], acc[mt][nt][1]);
            *(float2*)(C + (long)(mA + 8) * NPIX + n) = make_float2(acc[mt][nt][2], acc[mt][nt][3]);
        }
    }
}

// ============ merged P + F projection GEMM (WIDE, 3 terms) =================
__global__ void __launch_bounds__(128, 2) projf_kernel(
    const fp16* __restrict__ xTh, const fp16* __restrict__ xTl,
    const fp16* __restrict__ xcTh, const fp16* __restrict__ xcTl,
    const fp16* __restrict__ Wbch, const fp16* __restrict__ Wbcl,
    const fp16* __restrict__ Wdh, const fp16* __restrict__ Wdl,
    fp16* __restrict__ Ph, fp16* __restrict__ Pl,
    fp16* __restrict__ Fh,
    const float* __restrict__ bias2, const float* __restrict__ bd)
{
    extern __shared__ __align__(16) fp16 dsm[];

    const int bx  = blockIdx.x;
    const int tid = threadIdx.x;
    const int wid = tid >> 5;
    const int lane = tid & 31;
    const int wm = wid >> 1;
    const int wn = wid & 1;
    const uint32_t s0 = smem_u32(dsm);

    const fp16 *a0, *a1, *a2, *b0, *b1, *b2;
    fp16 *Hz, *Lz;
    const float* bias;
    int biasmode, ldc, m0, n0;
    const int lda = CH, ldb = CH;

    if (bx < 128) {                       // P projection
        int z = bx >> 5, my = bx & 31;
        m0 = my * 128; n0 = 0;
        a0 = xTh + (long)z * BS_XT; a1 = xTl + (long)z * BS_XT; a2 = a0;
        b0 = Wbch; b1 = Wbch; b2 = Wbcl;
        Hz = Ph + (long)z * BS_P; Lz = Pl + (long)z * BS_P;
        bias = bias2; biasmode = 2; ldc = 128;
    } else {                              // F projection
        int idx = bx - 128;
        int z = idx >> 7, r = idx & 127;
        m0 = (r & 3) * 128; n0 = (r >> 2) * 128;
        a0 = Wdh; a1 = Wdl; a2 = Wdh;
        b0 = xcTh + (long)z * BS_XT; b1 = b0; b2 = xcTl + (long)z * BS_XT;
        Hz = Fh + (long)z * BS_F; Lz = nullptr;
        bias = bd; biasmode = 1; ldc = NPIX;
    }
    const int nkt = 3 * CH / 32;          // 48

    float acc[4][8][4];
#pragma unroll
    for (int i = 0; i < 4; i++)
#pragma unroll
        for (int j = 0; j < 8; j++)
#pragma unroll
            for (int q = 0; q < 4; q++) acc[i][j][q] = 0.0f;

    const int lrow0 = tid >> 2;
    const int lch0  = tid & 3;
#define LOAD_G(g, slot) do {                                                   \
        const int t_ = (g) % 3;                                                \
        const int k0_ = ((g) / 3) * 32;                                        \
        const fp16* Ap = (t_ == 0 ? a0 : (t_ == 1 ? a1 : a2)) + (long)m0 * lda + k0_; \
        const fp16* Bp = (t_ == 0 ? b0 : (t_ == 1 ? b1 : b2)) + (long)n0 * ldb + k0_; \
        const uint32_t da_ = s0 + (slot) * STAGE_B;                            \
        const uint32_t db_ = da_ + 128 * 80;                                   \
        _Pragma("unroll")                                                      \
        for (int i_ = 0; i_ < 4; i_++) {                                       \
            int row_ = lrow0 + i_ * 32;                                        \
            cp16(da_ + row_ * 80 + lch0 * 16, Ap + (long)row_ * lda + lch0 * 8);\
            cp16(db_ + row_ * 80 + lch0 * 16, Bp + (long)row_ * ldb + lch0 * 8);\
        }                                                                      \
        asm volatile("cp.async.commit_group;");                                \
    } while (0)

    GEMM_MAINLOOP_W(LOAD_G)
#undef LOAD_G

#pragma unroll
    for (int mt = 0; mt < 4; mt++) {
        const int mA = m0 + wm * 64 + mt * 16 + (lane >> 2);
        float bvA = 0.0f, bvB = 0.0f;
        if (biasmode == 1) { bvA = bias[mA] * g_scal[2]; bvB = bias[mA + 8] * g_scal[2]; }
#pragma unroll
        for (int nt = 0; nt < 8; nt++) {
            const int n = n0 + wn * 64 + nt * 8 + (lane & 3) * 2;
            float c0 = acc[mt][nt][0], c1 = acc[mt][nt][1];
            float c2 = acc[mt][nt][2], c3 = acc[mt][nt][3];
            if (biasmode == 1) { c0 += bvA; c1 += bvA; c2 += bvB; c3 += bvB; }
            else               { float b0v = bias[n], b1v = bias[n + 1];
                                 c0 += b0v; c1 += b1v; c2 += b0v; c3 += b1v; }
            if (Lz) {
                fp16 h0, l0, h1, l1, h2, l2, h3, l3;
                split2(c0, h0, l0); split2(c1, h1, l1);
                split2(c2, h2, l2); split2(c3, h3, l3);
                __half2 H0; H0.x = h0; H0.y = h1;
                __half2 H1; H1.x = h2; H1.y = h3;
                __half2 L0; L0.x = l0; L0.y = l1;
                __half2 L1; L1.x = l2; L1.y = l3;
                *(__half2*)(Hz + (long)mA * ldc + n)       = H0;
                *(__half2*)(Hz + (long)(mA + 8) * ldc + n) = H1;
                *(__half2*)(Lz + (long)mA * ldc + n)       = L0;
                *(__half2*)(Lz + (long)(mA + 8) * ldc + n) = L1;
            } else {
                __half2 H0; H0.x = __float2half_rn(c0); H0.y = __float2half_rn(c1);
                __half2 H1; H1.x = __float2half_rn(c2); H1.y = __float2half_rn(c3);
                *(__half2*)(Hz + (long)mA * ldc + n)       = H0;
                *(__half2*)(Hz + (long)(mA + 8) * ldc + n) = H1;
            }
        }
    }
}

// ============ WIDE out-GEMM (per-batch) ==========
__global__ void __launch_bounds__(128, 2) outgemm_wide_kernel(
    const fp16* __restrict__ A, const fp16* __restrict__ B,
    float* __restrict__ C, int batch)
{
    extern __shared__ __align__(16) fp16 dsm[];

    const int tid = threadIdx.x;
    const int wid = tid >> 5;
    const int lane = tid & 31;
    const int wm = wid >> 1;
    const int wn = wid & 1;
    const int m0 = blockIdx.x * 128;
    const int n0 = blockIdx.y * 128;
    const uint32_t s0 = smem_u32(dsm);

    const fp16* Ap0 = A + (long)batch * BS_F + (long)m0 * NPIX;
    const fp16* Bp0 = B + (long)batch * BS_S + (long)n0 * NPIX;
    float* Cz = C + (long)batch * BS_F;
    const int nkt = NPIX / 32;

    float acc[4][8][4];
#pragma unroll
    for (int i = 0; i < 4; i++)
#pragma unroll
        for (int j = 0; j < 8; j++)
#pragma unroll
            for (int q = 0; q < 4; q++) acc[i][j][q] = 0.0f;

    const int lrow0 = tid >> 2;
    const int lch0  = tid & 3;
#define LOAD_W(g, slot) do {                                                   \
        const int k0_ = (g) * 32;                                              \
        const uint32_t da_ = s0 + (slot) * STAGE_B;                            \
        const uint32_t db_ = da_ + 128 * 80;                                   \
        _Pragma("unroll")                                                      \
        for (int i_ = 0; i_ < 4; i_++) {                                       \
            int row_ = lrow0 + i_ * 32;                                        \
            cp16(da_ + row_ * 80 + lch0 * 16, Ap0 + (long)row_ * NPIX + k0_ + lch0 * 8); \
            cp16(db_ + row_ * 80 + lch0 * 16, Bp0 + (long)row_ * NPIX + k0_ + lch0 * 8); \
        }                                                                      \
        asm volatile("cp.async.commit_group;");                                \
    } while (0)

    GEMM_MAINLOOP_W(LOAD_W)
#undef LOAD_W

#pragma unroll
    for (int mt = 0; mt < 4; mt++) {
        const int mA = m0 + wm * 64 + mt * 16 + (lane >> 2);
#pragma unroll
        for (int nt = 0; nt < 8; nt++) {
            const int n = n0 + wn * 64 + nt * 8 + (lane & 3) * 2;
            *(float2*)(Cz + (long)mA * NPIX + n)       = make_float2(acc[mt][nt][0], acc[mt][nt][1]);
            *(float2*)(Cz + (long)(mA + 8) * NPIX + n) = make_float2(acc[mt][nt][2], acc[mt][nt][3]);
        }
    }
}

// ---------------- launch ----------------
extern "C" void kernel_launch(void* const* d_in, const int* in_sizes, int n_in,
                              void* d_out, int out_size) {
    const float* x1    = (const float*)d_in[0];
    const float* x2    = (const float*)d_in[1];
    const float* Wb    = (const float*)d_in[2];
    const float* bb    = (const float*)d_in[3];
    const float* Wc    = (const float*)d_in[4];
    const float* bc    = (const float*)d_in[5];
    const float* Wdd   = (const float*)d_in[6];
    const float* bd    = (const float*)d_in[7];
    const float* alpha = (const float*)d_in[8];
    const float* beta  = (const float*)d_in[9];
    float* out = (float*)d_out;

    fp16 *xTh, *xTl, *xcTh, *xcTl, *Wbch, *Wbcl, *Wdh, *Wdl, *Ph, *Pl, *Fh, *Ah;
    float *S12, *S21, *bias2;
    cudaGetSymbolAddress((void**)&xTh,  g_xTh);
    cudaGetSymbolAddress((void**)&xTl,  g_xTl);
    cudaGetSymbolAddress((void**)&xcTh, g_xcTh);
    cudaGetSymbolAddress((void**)&xcTl, g_xcTl);
    cudaGetSymbolAddress((void**)&Wbch, g_Wbch);
    cudaGetSymbolAddress((void**)&Wbcl, g_Wbcl);
    cudaGetSymbolAddress((void**)&Wdh,  g_Wdh);
    cudaGetSymbolAddress((void**)&Wdl,  g_Wdl);
    cudaGetSymbolAddress((void**)&Ph,   g_Ph);
    cudaGetSymbolAddress((void**)&Pl,   g_Pl);
    cudaGetSymbolAddress((void**)&Fh,   g_Fh);
    cudaGetSymbolAddress((void**)&S12,  g_S12);
    cudaGetSymbolAddress((void**)&S21,  g_S21);
    cudaGetSymbolAddress((void**)&Ah,   g_Ah);
    cudaGetSymbolAddress((void**)&bias2, g_bias2);

    cudaFuncSetAttribute(projf_kernel,
                         cudaFuncAttributeMaxDynamicSharedMemorySize, SMEM_DYN);
    cudaFuncSetAttribute(logits_kernel,
                         cudaFuncAttributeMaxDynamicSharedMemorySize, SMEM_DYN);
    cudaFuncSetAttribute(outgemm_wide_kernel,
                         cudaFuncAttributeMaxDynamicSharedMemorySize, SMEM_DYN);

    prep_kernel<<<1, 128>>>(bb, bc, alpha, beta);

    dim3 gT(NPIX / 32, CH / 32, BATCH);
    transcomb_kernel<<<gT, dim3(32, 8)>>>(x1, x2);

    wbc_split_kernel<<<(128 * CH + 255) / 256, 256>>>(Wb, Wc);
    split_kernel<<<(CH * CH + 255) / 256, 256>>>(Wdd, Wdh, Wdl, CH * CH);

    // merged P + F projections (wide): 384 CTAs x 128 threads
    projf_kernel<<<384, 128, SMEM_DYN>>>(
        xTh, xTl, xcTh, xcTl, Wbch, Wbcl, Wdh, Wdl, Ph, Pl, Fh, bias2, bd);

    // per-batch pipeline: logits(b) -> softdiff(b) -> out(b).
    // One batch's S12+S21 (128 MB) ~ fits L2, so softdiff reads mostly hit L2;
    // Ah(b) (32 MB) stays L2-hot for the out-GEMM.
    for (int b = 0; b < BATCH; b++) {
        logits_kernel<<<dim3(NPIX / 128, NPIX / 128, 2), 128, SMEM_DYN>>>(
            Ph, Pl, S12, S21, b);
        softdiff_kernel<<<NPIX, 256>>>(b);
        outgemm_wide_kernel<<<dim3(CH / 128, NPIX / 128, 1), 128, SMEM_DYN>>>(
            Fh, Ah, out, b);
    }
}

// round 15
// speedup vs baseline: 1.1259x; 1.1259x over previous
#include <cuda_runtime.h>
#include <cuda_fp16.h>
#include <math.h>
#include <stdint.h>

#define BATCH 2
#define CH    512
#define CQ    64
#define NPIX  4096

#define BS_XT (NPIX * CH)
#define BS_P  (NPIX * 128)
#define BS_F  (CH * NPIX)
#define BS_S  ((long)NPIX * NPIX)

typedef __half fp16;

// ---------------- static scratch ----------------
__device__ __align__(128) fp16  g_xTh[4L * NPIX * CH];
__device__ __align__(128) fp16  g_xTl[4L * NPIX * CH];
__device__ __align__(128) fp16  g_xcTh[2L * NPIX * CH];
__device__ __align__(128) fp16  g_xcTl[2L * NPIX * CH];
__device__ __align__(128) fp16  g_Wbch[128 * CH];
__device__ __align__(128) fp16  g_Wbcl[128 * CH];
__device__ __align__(128) fp16  g_Wdh[CH * CH];
__device__ __align__(128) fp16  g_Wdl[CH * CH];
__device__ __align__(128) fp16  g_Ph[4L * NPIX * 128];
__device__ __align__(128) fp16  g_Pl[4L * NPIX * 128];
__device__ __align__(128) fp16  g_Fh[(long)BATCH * CH * NPIX];
__device__ __align__(128) float g_S12[(size_t)BATCH * NPIX * NPIX];
__device__ __align__(128) float g_S21[(size_t)BATCH * NPIX * NPIX];
__device__ __align__(128) fp16  g_Ah[(size_t)BATCH * NPIX * NPIX];
__device__ float g_scal[4];
__device__ float g_bias2[128];

__device__ __forceinline__ void split2(float v, fp16& h, fp16& l) {
    h = __float2half_rn(v);
    l = __float2half_rn(v - __half2float(h));
}

__device__ __forceinline__ float fexp(float x) {
    float t = x * 1.4426950408889634f;
    t = fmaxf(t, -125.0f);
    float r = rintf(t);
    float f = t - r;
    float p = 1.3333558e-3f;
    p = fmaf(p, f, 9.6181291e-3f);
    p = fmaf(p, f, 5.5504109e-2f);
    p = fmaf(p, f, 2.4022651e-1f);
    p = fmaf(p, f, 6.9314718e-1f);
    p = fmaf(p, f, 1.0f);
    float sc = __int_as_float(((int)r + 127) << 23);
    return p * sc;
}

// ---------------- prep ----------------
__global__ void prep_kernel(const float* bb, const float* bc,
                            const float* a, const float* b) {
    int t = threadIdx.x;
    if (t < 64)       g_bias2[t] = bb[t];
    else if (t < 128) g_bias2[t] = bc[t - 64];
    if (t == 0) { g_scal[0] = a[0]; g_scal[1] = b[0]; g_scal[2] = a[0] + b[0]; }
}

__global__ void split_kernel(const float* __restrict__ src,
                             fp16* __restrict__ hi, fp16* __restrict__ lo, int n) {
    int i = blockIdx.x * blockDim.x + threadIdx.x;
    if (i < n) { fp16 h, l; split2(src[i], h, l); hi[i] = h; lo[i] = l; }
}

__global__ void wbc_split_kernel(const float* __restrict__ Wb,
                                 const float* __restrict__ Wc) {
    int i = blockIdx.x * blockDim.x + threadIdx.x;
    if (i < 128 * CH) {
        float v = (i < 64 * CH) ? Wb[i] : Wc[i - 64 * CH];
        fp16 h, l; split2(v, h, l);
        g_Wbch[i] = h; g_Wbcl[i] = l;
    }
}

// ---------------- combine + transpose + split ----------------
__global__ void __launch_bounds__(256) transcomb_kernel(
    const float* __restrict__ x1, const float* __restrict__ x2) {
    __shared__ float t1[32][33], t2[32][33];
    const int b  = blockIdx.z;
    const int n0 = blockIdx.x * 32;
    const int k0 = blockIdx.y * 32;
    const int tx = threadIdx.x, ty = threadIdx.y;
    const float al = g_scal[0], be = g_scal[1];

    const long inb = (long)b * CH * NPIX;
#pragma unroll
    for (int it = 0; it < 4; it++) {
        int ki = ty + it * 8;
        t1[ki][tx] = x1[inb + (long)(k0 + ki) * NPIX + n0 + tx];
        t2[ki][tx] = x2[inb + (long)(k0 + ki) * NPIX + n0 + tx];
    }
    __syncthreads();

#pragma unroll
    for (int it = 0; it < 4; it++) {
        int ni = ty + it * 8;
        float v1 = t1[tx][ni];
        float v2 = t2[tx][ni];
        float vc = al * v1 + be * v2;
        long o1 = ((long)b * NPIX + n0 + ni) * CH + k0 + tx;
        long o2 = ((long)(2 + b) * NPIX + n0 + ni) * CH + k0 + tx;
        long oc = ((long)b * NPIX + n0 + ni) * CH + k0 + tx;
        fp16 h, l;
        split2(v1, h, l); g_xTh[o1] = h; g_xTl[o1] = l;
        split2(v2, h, l); g_xTh[o2] = h; g_xTl[o2] = l;
        split2(vc, h, l); g_xcTh[oc] = h; g_xcTl[oc] = l;
    }
}

// ---------------- fused double-softmax abs-diff (streaming loads) ----------
__global__ void __launch_bounds__(256) softdiff_kernel() {
    const long row = blockIdx.x;
    const float4* p12 = (const float4*)(g_S12 + row * (long)NPIX);
    const float4* p21 = (const float4*)(g_S21 + row * (long)NPIX);
    __half2* oh = (__half2*)(g_Ah + row * (long)NPIX);
    const int t = threadIdx.x;
    constexpr int PER = NPIX / (256 * 4);

    float4 v12[PER], v21[PER];
    float mx12 = -1e30f, mx21 = -1e30f;
#pragma unroll
    for (int i = 0; i < PER; i++) {
        v12[i] = __ldcs(&p12[t + i * 256]);
        v21[i] = __ldcs(&p21[t + i * 256]);
        mx12 = fmaxf(mx12, fmaxf(fmaxf(v12[i].x, v12[i].y), fmaxf(v12[i].z, v12[i].w)));
        mx21 = fmaxf(mx21, fmaxf(fmaxf(v21[i].x, v21[i].y), fmaxf(v21[i].z, v21[i].w)));
    }
    __shared__ float red[2][8];
#pragma unroll
    for (int o = 16; o > 0; o >>= 1) {
        mx12 = fmaxf(mx12, __shfl_xor_sync(0xffffffffu, mx12, o));
        mx21 = fmaxf(mx21, __shfl_xor_sync(0xffffffffu, mx21, o));
    }
    if ((t & 31) == 0) { red[0][t >> 5] = mx12; red[1][t >> 5] = mx21; }
    __syncthreads();
    mx12 = red[0][0]; mx21 = red[1][0];
#pragma unroll
    for (int w = 1; w < 8; w++) {
        mx12 = fmaxf(mx12, red[0][w]);
        mx21 = fmaxf(mx21, red[1][w]);
    }
    __syncthreads();

    float s12 = 0.0f, s21 = 0.0f;
#pragma unroll
    for (int i = 0; i < PER; i++) {
        v12[i].x = fexp(v12[i].x - mx12); v12[i].y = fexp(v12[i].y - mx12);
        v12[i].z = fexp(v12[i].z - mx12); v12[i].w = fexp(v12[i].w - mx12);
        v21[i].x = fexp(v21[i].x - mx21); v21[i].y = fexp(v21[i].y - mx21);
        v21[i].z = fexp(v21[i].z - mx21); v21[i].w = fexp(v21[i].w - mx21);
        s12 += (v12[i].x + v12[i].y) + (v12[i].z + v12[i].w);
        s21 += (v21[i].x + v21[i].y) + (v21[i].z + v21[i].w);
    }
#pragma unroll
    for (int o = 16; o > 0; o >>= 1) {
        s12 += __shfl_xor_sync(0xffffffffu, s12, o);
        s21 += __shfl_xor_sync(0xffffffffu, s21, o);
    }
    if ((t & 31) == 0) { red[0][t >> 5] = s12; red[1][t >> 5] = s21; }
    __syncthreads();
    s12 = red[0][0]; s21 = red[1][0];
#pragma unroll
    for (int w = 1; w < 8; w++) { s12 += red[0][w]; s21 += red[1][w]; }

    const float i12 = 1.0f / s12;
    const float i21 = 1.0f / s21;
#pragma unroll
    for (int i = 0; i < PER; i++) {
        float a0 = fabsf(v12[i].x * i12 - v21[i].x * i21);
        float a1 = fabsf(v12[i].y * i12 - v21[i].y * i21);
        float a2 = fabsf(v12[i].z * i12 - v21[i].z * i21);
        float a3 = fabsf(v12[i].w * i12 - v21[i].w * i21);
        __half2 h0; h0.x = __float2half_rn(a0); h0.y = __float2half_rn(a1);
        __half2 h1; h1.x = __float2half_rn(a2); h1.y = __float2half_rn(a3);
        __stcs(&oh[(t + i * 256) * 2],     h0);
        __stcs(&oh[(t + i * 256) * 2 + 1], h1);
    }
}

// ================= shared HMMA machinery (4-stage, WIDE 4-warp) ============
#define STAGE_B (2 * 128 * 80)
#define NSTAGE  4
#define SMEM_DYN (NSTAGE * STAGE_B)   // 81920

__device__ __forceinline__ uint32_t smem_u32(const void* p) {
    uint32_t a;
    asm("{ .reg .u64 t; cvta.to.shared.u64 t, %1; cvt.u32.u64 %0, t; }" : "=r"(a) : "l"(p));
    return a;
}
__device__ __forceinline__ void cp16(uint32_t dst, const void* src) {
    asm volatile("cp.async.cg.shared.global [%0], [%1], 16;" :: "r"(dst), "l"(src));
}
__device__ __forceinline__ void ldsm4(uint32_t* r, uint32_t addr) {
    asm volatile("ldmatrix.sync.aligned.m8n8.x4.shared.b16 {%0,%1,%2,%3}, [%4];"
                 : "=r"(r[0]), "=r"(r[1]), "=r"(r[2]), "=r"(r[3]) : "r"(addr));
}
__device__ __forceinline__ void mma16816(float* d, const uint32_t* a, const uint32_t* b) {
    asm volatile(
        "mma.sync.aligned.m16n8k16.row.col.f32.f16.f16.f32 "
        "{%0,%1,%2,%3}, {%4,%5,%6,%7}, {%8,%9}, {%0,%1,%2,%3};"
        : "+f"(d[0]), "+f"(d[1]), "+f"(d[2]), "+f"(d[3])
        : "r"(a[0]), "r"(a[1]), "r"(a[2]), "r"(a[3]), "r"(b[0]), "r"(b[1]));
}
__device__ __forceinline__ void waitg(int pend) {
    if (pend >= 2)      asm volatile("cp.async.wait_group 2;");
    else if (pend == 1) asm volatile("cp.async.wait_group 1;");
    else                asm volatile("cp.async.wait_group 0;");
}
__device__ __forceinline__ void stcs2(float* addr, float a, float b) {
    asm volatile("st.global.cs.v2.f32 [%0], {%1, %2};" :: "l"(addr), "f"(a), "f"(b) : "memory");
}

// WIDE mainloop: 128 threads, 4 warps of 64x64, acc[4][8][4]
#define GEMM_MAINLOOP_W(LOADER)                                                \
    LOADER(0, 0);                                                              \
    if (nkt > 1) LOADER(1, 1);                                                 \
    if (nkt > 2) LOADER(2, 2);                                                 \
    int cons = 0, ld = 3;                                                      \
    for (int g = 0; g < nkt; g++) {                                            \
        waitg(nkt - 1 - g);                                                    \
        __syncthreads();                                                       \
        if (g + 3 < nkt) { LOADER(g + 3, ld); ld++; if (ld == NSTAGE) ld = 0; }\
        const uint32_t da = s0 + cons * STAGE_B;                               \
        const uint32_t db = da + 128 * 80;                                     \
        _Pragma("unroll")                                                      \
        for (int ks = 0; ks < 2; ks++) {                                       \
            uint32_t af[4][4];                                                 \
            _Pragma("unroll")                                                  \
            for (int mt = 0; mt < 4; mt++) {                                   \
                int row = wm * 64 + mt * 16 + (lane & 15);                     \
                int kc  = ks * 16 + (lane >> 4) * 8;                           \
                ldsm4(af[mt], da + row * 80 + kc * 2);                         \
            }                                                                  \
            uint32_t bfr[4][4];                                                \
            _Pragma("unroll")                                                  \
            for (int p = 0; p < 4; p++) {                                      \
                int row = wn * 64 + p * 16 + (lane >> 4) * 8 + (lane & 7);     \
                int kc  = ks * 16 + ((lane >> 3) & 1) * 8;                     \
                ldsm4(bfr[p], db + row * 80 + kc * 2);                         \
            }                                                                  \
            _Pragma("unroll")                                                  \
            for (int mt = 0; mt < 4; mt++)                                     \
                _Pragma("unroll")                                              \
                for (int p = 0; p < 4; p++) {                                  \
                    mma16816(acc[mt][2 * p],     af[mt], &bfr[p][0]);          \
                    mma16816(acc[mt][2 * p + 1], af[mt], &bfr[p][2]);          \
                }                                                              \
        }                                                                      \
        cons++; if (cons == NSTAGE) cons = 0;                                  \
    }

// ================= merged logits GEMM (WIDE, z in [0,4), 3 TERMS) ==========
__global__ void __launch_bounds__(128, 2) logits_kernel(
    const fp16* __restrict__ Ph, const fp16* __restrict__ Pl,
    float* __restrict__ S12, float* __restrict__ S21)
{
    extern __shared__ __align__(16) fp16 dsm[];

    const int tid = threadIdx.x;
    const int wid = tid >> 5;
    const int lane = tid & 31;
    const int wm = wid >> 1;
    const int wn = wid & 1;
    const int m0 = blockIdx.y * 128;
    const int n0 = blockIdx.x * 128;
    const int z  = blockIdx.z;
    const int b  = z & 1;
    const int which = z >> 1;
    const uint32_t s0 = smem_u32(dsm);

    const int aPlane = which ? (2 + b) : b;
    const int bPlane = which ? b : (2 + b);
    const fp16* a0 = Ph + (long)aPlane * BS_P;
    const fp16* a1 = Pl + (long)aPlane * BS_P;
    const fp16* a2 = a0;
    const fp16* b0 = Ph + (long)bPlane * BS_P + 64;
    const fp16* b1 = b0;
    const fp16* b2 = Pl + (long)bPlane * BS_P + 64;
    float* C = (which ? S21 : S12) + (long)b * BS_S;

    const int nkt = 6, lda = 128, ldb = 128;

    float acc[4][8][4];
#pragma unroll
    for (int i = 0; i < 4; i++)
#pragma unroll
        for (int j = 0; j < 8; j++)
#pragma unroll
            for (int q = 0; q < 4; q++) acc[i][j][q] = 0.0f;

    const int lrow0 = tid >> 2;
    const int lch0  = tid & 3;
#define LOAD_G(g, slot) do {                                                   \
        const int t_ = (g) % 3;                                                \
        const int k0_ = ((g) / 3) * 32;                                        \
        const fp16* Ap = (t_ == 0 ? a0 : (t_ == 1 ? a1 : a2)) + (long)m0 * lda + k0_; \
        const fp16* Bp = (t_ == 0 ? b0 : (t_ == 1 ? b1 : b2)) + (long)n0 * ldb + k0_; \
        const uint32_t da_ = s0 + (slot) * STAGE_B;                            \
        const uint32_t db_ = da_ + 128 * 80;                                   \
        _Pragma("unroll")                                                      \
        for (int i_ = 0; i_ < 4; i_++) {                                       \
            int row_ = lrow0 + i_ * 32;                                        \
            cp16(da_ + row_ * 80 + lch0 * 16, Ap + (long)row_ * lda + lch0 * 8);\
            cp16(db_ + row_ * 80 + lch0 * 16, Bp + (long)row_ * ldb + lch0 * 8);\
        }                                                                      \
        asm volatile("cp.async.commit_group;");                                \
    } while (0)

    GEMM_MAINLOOP_W(LOAD_G)
#undef LOAD_G

#pragma unroll
    for (int mt = 0; mt < 4; mt++) {
        const int mA = m0 + wm * 64 + mt * 16 + (lane >> 2);
#pragma unroll
        for (int nt = 0; nt < 8; nt++) {
            const int n = n0 + wn * 64 + nt * 8 + (lane & 3) * 2;
            stcs2(C + (long)mA * NPIX + n,       acc[mt][nt][0], acc[mt][nt][1]);
            stcs2(C + (long)(mA + 8) * NPIX + n, acc[mt][nt][2], acc[mt][nt][3]);
        }
    }
}

// ============ merged P + F projection GEMM (WIDE, 3 terms) =================
__global__ void __launch_bounds__(128, 2) projf_kernel(
    const fp16* __restrict__ xTh, const fp16* __restrict__ xTl,
    const fp16* __restrict__ xcTh, const fp16* __restrict__ xcTl,
    const fp16* __restrict__ Wbch, const fp16* __restrict__ Wbcl,
    const fp16* __restrict__ Wdh, const fp16* __restrict__ Wdl,
    fp16* __restrict__ Ph, fp16* __restrict__ Pl,
    fp16* __restrict__ Fh,
    const float* __restrict__ bias2, const float* __restrict__ bd)
{
    extern __shared__ __align__(16) fp16 dsm[];

    const int bx  = blockIdx.x;
    const int tid = threadIdx.x;
    const int wid = tid >> 5;
    const int lane = tid & 31;
    const int wm = wid >> 1;
    const int wn = wid & 1;
    const uint32_t s0 = smem_u32(dsm);

    const fp16 *a0, *a1, *a2, *b0, *b1, *b2;
    fp16 *Hz, *Lz;
    const float* bias;
    int biasmode, ldc, m0, n0;
    const int lda = CH, ldb = CH;

    if (bx < 128) {                       // P projection
        int z = bx >> 5, my = bx & 31;
        m0 = my * 128; n0 = 0;
        a0 = xTh + (long)z * BS_XT; a1 = xTl + (long)z * BS_XT; a2 = a0;
        b0 = Wbch; b1 = Wbch; b2 = Wbcl;
        Hz = Ph + (long)z * BS_P; Lz = Pl + (long)z * BS_P;
        bias = bias2; biasmode = 2; ldc = 128;
    } else {                              // F projection
        int idx = bx - 128;
        int z = idx >> 7, r = idx & 127;
        m0 = (r & 3) * 128; n0 = (r >> 2) * 128;
        a0 = Wdh; a1 = Wdl; a2 = Wdh;
        b0 = xcTh + (long)z * BS_XT; b1 = b0; b2 = xcTl + (long)z * BS_XT;
        Hz = Fh + (long)z * BS_F; Lz = nullptr;
        bias = bd; biasmode = 1; ldc = NPIX;
    }
    const int nkt = 3 * CH / 32;          // 48

    float acc[4][8][4];
#pragma unroll
    for (int i = 0; i < 4; i++)
#pragma unroll
        for (int j = 0; j < 8; j++)
#pragma unroll
            for (int q = 0; q < 4; q++) acc[i][j][q] = 0.0f;

    const int lrow0 = tid >> 2;
    const int lch0  = tid & 3;
#define LOAD_G(g, slot) do {                                                   \
        const int t_ = (g) % 3;                                                \
        const int k0_ = ((g) / 3) * 32;                                        \
        const fp16* Ap = (t_ == 0 ? a0 : (t_ == 1 ? a1 : a2)) + (long)m0 * lda + k0_; \
        const fp16* Bp = (t_ == 0 ? b0 : (t_ == 1 ? b1 : b2)) + (long)n0 * ldb + k0_; \
        const uint32_t da_ = s0 + (slot) * STAGE_B;                            \
        const uint32_t db_ = da_ + 128 * 80;                                   \
        _Pragma("unroll")                                                      \
        for (int i_ = 0; i_ < 4; i_++) {                                       \
            int row_ = lrow0 + i_ * 32;                                        \
            cp16(da_ + row_ * 80 + lch0 * 16, Ap + (long)row_ * lda + lch0 * 8);\
            cp16(db_ + row_ * 80 + lch0 * 16, Bp + (long)row_ * ldb + lch0 * 8);\
        }                                                                      \
        asm volatile("cp.async.commit_group;");                                \
    } while (0)

    GEMM_MAINLOOP_W(LOAD_G)
#undef LOAD_G

#pragma unroll
    for (int mt = 0; mt < 4; mt++) {
        const int mA = m0 + wm * 64 + mt * 16 + (lane >> 2);
        float bvA = 0.0f, bvB = 0.0f;
        if (biasmode == 1) { bvA = bias[mA] * g_scal[2]; bvB = bias[mA + 8] * g_scal[2]; }
#pragma unroll
        for (int nt = 0; nt < 8; nt++) {
            const int n = n0 + wn * 64 + nt * 8 + (lane & 3) * 2;
            float c0 = acc[mt][nt][0], c1 = acc[mt][nt][1];
            float c2 = acc[mt][nt][2], c3 = acc[mt][nt][3];
            if (biasmode == 1) { c0 += bvA; c1 += bvA; c2 += bvB; c3 += bvB; }
            else               { float b0v = bias[n], b1v = bias[n + 1];
                                 c0 += b0v; c1 += b1v; c2 += b0v; c3 += b1v; }
            if (Lz) {
                fp16 h0, l0, h1, l1, h2, l2, h3, l3;
                split2(c0, h0, l0); split2(c1, h1, l1);
                split2(c2, h2, l2); split2(c3, h3, l3);
                __half2 H0; H0.x = h0; H0.y = h1;
                __half2 H1; H1.x = h2; H1.y = h3;
                __half2 L0; L0.x = l0; L0.y = l1;
                __half2 L1; L1.x = l2; L1.y = l3;
                *(__half2*)(Hz + (long)mA * ldc + n)       = H0;
                *(__half2*)(Hz + (long)(mA + 8) * ldc + n) = H1;
                *(__half2*)(Lz + (long)mA * ldc + n)       = L0;
                *(__half2*)(Lz + (long)(mA + 8) * ldc + n) = L1;
            } else {
                __half2 H0; H0.x = __float2half_rn(c0); H0.y = __float2half_rn(c1);
                __half2 H1; H1.x = __float2half_rn(c2); H1.y = __float2half_rn(c3);
                *(__half2*)(Hz + (long)mA * ldc + n)       = H0;
                *(__half2*)(Hz + (long)(mA + 8) * ldc + n) = H1;
            }
        }
    }
}

// ============ WIDE out-GEMM (z = batch) ==========
__global__ void __launch_bounds__(128, 2) outgemm_wide_kernel(
    const fp16* __restrict__ A, const fp16* __restrict__ B,
    float* __restrict__ C)
{
    extern __shared__ __align__(16) fp16 dsm[];

    const int tid = threadIdx.x;
    const int wid = tid >> 5;
    const int lane = tid & 31;
    const int wm = wid >> 1;
    const int wn = wid & 1;
    const int m0 = blockIdx.x * 128;
    const int n0 = blockIdx.y * 128;
    const int z  = blockIdx.z;
    const uint32_t s0 = smem_u32(dsm);

    const fp16* Ap0 = A + (long)z * BS_F + (long)m0 * NPIX;
    const fp16* Bp0 = B + (long)z * BS_S + (long)n0 * NPIX;
    float* Cz = C + (long)z * BS_F;
    const int nkt = NPIX / 32;

    float acc[4][8][4];
#pragma unroll
    for (int i = 0; i < 4; i++)
#pragma unroll
        for (int j = 0; j < 8; j++)
#pragma unroll
            for (int q = 0; q < 4; q++) acc[i][j][q] = 0.0f;

    const int lrow0 = tid >> 2;
    const int lch0  = tid & 3;
#define LOAD_W(g, slot) do {                                                   \
        const int k0_ = (g) * 32;                                              \
        const uint32_t da_ = s0 + (slot) * STAGE_B;                            \
        const uint32_t db_ = da_ + 128 * 80;                                   \
        _Pragma("unroll")                                                      \
        for (int i_ = 0; i_ < 4; i_++) {                                       \
            int row_ = lrow0 + i_ * 32;                                        \
            cp16(da_ + row_ * 80 + lch0 * 16, Ap0 + (long)row_ * NPIX + k0_ + lch0 * 8); \
            cp16(db_ + row_ * 80 + lch0 * 16, Bp0 + (long)row_ * NPIX + k0_ + lch0 * 8); \
        }                                                                      \
        asm volatile("cp.async.commit_group;");                                \
    } while (0)

    GEMM_MAINLOOP_W(LOAD_W)
#undef LOAD_W

#pragma unroll
    for (int mt = 0; mt < 4; mt++) {
        const int mA = m0 + wm * 64 + mt * 16 + (lane >> 2);
#pragma unroll
        for (int nt = 0; nt < 8; nt++) {
            const int n = n0 + wn * 64 + nt * 8 + (lane & 3) * 2;
            *(float2*)(Cz + (long)mA * NPIX + n)       = make_float2(acc[mt][nt][0], acc[mt][nt][1]);
            *(float2*)(Cz + (long)(mA + 8) * NPIX + n) = make_float2(acc[mt][nt][2], acc[mt][nt][3]);
        }
    }
}

// ---------------- launch ----------------
extern "C" void kernel_launch(void* const* d_in, const int* in_sizes, int n_in,
                              void* d_out, int out_size) {
    const float* x1    = (const float*)d_in[0];
    const float* x2    = (const float*)d_in[1];
    const float* Wb    = (const float*)d_in[2];
    const float* bb    = (const float*)d_in[3];
    const float* Wc    = (const float*)d_in[4];
    const float* bc    = (const float*)d_in[5];
    const float* Wdd   = (const float*)d_in[6];
    const float* bd    = (const float*)d_in[7];
    const float* alpha = (const float*)d_in[8];
    const float* beta  = (const float*)d_in[9];
    float* out = (float*)d_out;

    fp16 *xTh, *xTl, *xcTh, *xcTl, *Wbch, *Wbcl, *Wdh, *Wdl, *Ph, *Pl, *Fh, *Ah;
    float *S12, *S21, *bias2;
    cudaGetSymbolAddress((void**)&xTh,  g_xTh);
    cudaGetSymbolAddress((void**)&xTl,  g_xTl);
    cudaGetSymbolAddress((void**)&xcTh, g_xcTh);
    cudaGetSymbolAddress((void**)&xcTl, g_xcTl);
    cudaGetSymbolAddress((void**)&Wbch, g_Wbch);
    cudaGetSymbolAddress((void**)&Wbcl, g_Wbcl);
    cudaGetSymbolAddress((void**)&Wdh,  g_Wdh);
    cudaGetSymbolAddress((void**)&Wdl,  g_Wdl);
    cudaGetSymbolAddress((void**)&Ph,   g_Ph);
    cudaGetSymbolAddress((void**)&Pl,   g_Pl);
    cudaGetSymbolAddress((void**)&Fh,   g_Fh);
    cudaGetSymbolAddress((void**)&S12,  g_S12);
    cudaGetSymbolAddress((void**)&S21,  g_S21);
    cudaGetSymbolAddress((void**)&Ah,   g_Ah);
    cudaGetSymbolAddress((void**)&bias2, g_bias2);

    cudaFuncSetAttribute(projf_kernel,
                         cudaFuncAttributeMaxDynamicSharedMemorySize, SMEM_DYN);
    cudaFuncSetAttribute(logits_kernel,
                         cudaFuncAttributeMaxDynamicSharedMemorySize, SMEM_DYN);
    cudaFuncSetAttribute(outgemm_wide_kernel,
                         cudaFuncAttributeMaxDynamicSharedMemorySize, SMEM_DYN);

    prep_kernel<<<1, 128>>>(bb, bc, alpha, beta);

    dim3 gT(NPIX / 32, CH / 32, BATCH);
    transcomb_kernel<<<gT, dim3(32, 8)>>>(x1, x2);

    wbc_split_kernel<<<(128 * CH + 255) / 256, 256>>>(Wb, Wc);
    split_kernel<<<(CH * CH + 255) / 256, 256>>>(Wdd, Wdh, Wdl, CH * CH);

    // merged P + F projections (wide): 384 CTAs x 128 threads
    projf_kernel<<<384, 128, SMEM_DYN>>>(
        xTh, xTl, xcTh, xcTl, Wbch, Wbcl, Wdh, Wdl, Ph, Pl, Fh, bias2, bd);

    // merged logits (wide, 3 terms): S12 (z=0,1) and S21 (z=2,3)
    logits_kernel<<<dim3(NPIX / 128, NPIX / 128, 4), 128, SMEM_DYN>>>(
        Ph, Pl, S12, S21);

    // att = |softmax(S12)-softmax(S21)| -> fp16 (FMA exp, streaming)
    softdiff_kernel<<<BATCH * NPIX, 256>>>();

    // out[c,n] = sum_m Fh[c,m]*Ah[n,m], wide kernel, SWAP grid
    outgemm_wide_kernel<<<dim3(CH / 128, NPIX / 128, BATCH), 128, SMEM_DYN>>>(
        Fh, Ah, out);
}